// round 7
// baseline (speedup 1.0000x reference)
#include <cuda_runtime.h>
#include <cstdint>

// Shape fixed by the reference
#define DD 64
#define HH 256
#define ROWS 64            // rows per block
#define THREADS 512        // 16 warps -> 4 warps per SMSP
#define HPAD 260           // h row stride (floats); de-conflicted for col reads

// smem layout (floats)
#define OFF_W1 0
#define OFF_W2 (OFF_W1 + DD*HH)           // 16384
#define OFF_Y  (OFF_W2 + HH*DD)           // +16384
#define OFF_H  (OFF_Y + ROWS*DD)          // +4096
#define OFF_Z  (OFF_H + ROWS*HPAD)        // +16640
#define OFF_S  (OFF_Z + HH)
#define OFF_B2 (OFF_S + HH)
#define SMEM_FLOATS (OFF_B2 + DD)
#define SMEM_BYTES  (SMEM_FLOATS * sizeof(float))   // ~212 KB

__device__ __forceinline__ float tanh_ap(float x) {
    float r;
    asm("tanh.approx.f32 %0, %1;" : "=f"(r) : "f"(x));
    return r;
}

__global__ __launch_bounds__(THREADS, 1)
void ode_kernel(const float* __restrict__ tptr, const float* __restrict__ y,
                const float* __restrict__ W1, const float* __restrict__ b1,
                const float* __restrict__ wt, const float* __restrict__ W2,
                const float* __restrict__ b2, float* __restrict__ out)
{
    extern __shared__ float sm[];
    float* sW1 = sm + OFF_W1;   // [64][256]
    float* sW2 = sm + OFF_W2;   // [256][64]
    float* sy  = sm + OFF_Y;    // [64][64]
    float* sh  = sm + OFF_H;    // [64][HPAD]
    float* sz  = sm + OFF_Z;    // [256]
    float* ss  = sm + OFF_S;    // [256]
    float* sb2 = sm + OFF_B2;   // [64]

    const int tid = threadIdx.x;

    // ---- stage weights + y tile (coalesced float4) ----
    {
        const float4* src = (const float4*)W1;
        float4* dst = (float4*)sW1;
        #pragma unroll
        for (int i = 0; i < (DD*HH)/4/THREADS; i++)
            dst[tid + i*THREADS] = src[tid + i*THREADS];
        src = (const float4*)W2; dst = (float4*)sW2;
        #pragma unroll
        for (int i = 0; i < (HH*DD)/4/THREADS; i++)
            dst[tid + i*THREADS] = src[tid + i*THREADS];
        const float4* ys = (const float4*)(y + (size_t)blockIdx.x * ROWS * DD);
        float4* yd = (float4*)sy;
        #pragma unroll
        for (int i = 0; i < (ROWS*DD)/4/THREADS; i++)
            yd[tid + i*THREADS] = ys[tid + i*THREADS];
    }
    // ---- small constants (gmem, cheap) ----
    if (tid < HH) {
        const float tv = tptr[0];
        sz[tid] = tv * wt[tid] + b1[tid];
        if (tid < DD) sb2[tid] = b2[tid];
    }
    __syncthreads();

    // ---- s_j = sum_d W1[d,j]*W2[j,d] from smem (runs concurrent with phase 1 setup) ----
    if (tid < HH) {
        float s = 0.f;
        #pragma unroll
        for (int d = 0; d < DD; d++)
            s += sW1[d*HH + tid] * sW2[tid*DD + d];
        ss[tid] = s;
    }

    // =========== Phase 1: H = tanh(Y @ W1 + z), 4x8 tile / thread ===========
    {
        const int warp = tid >> 5;        // 0..15 -> 4-row stripe
        const int lane = tid & 31;        // -> 8-col stripe
        const int r0 = warp * 4, c0 = lane * 8;

        float acc[4][8];
        {
            float4 z0 = *(const float4*)(sz + c0);
            float4 z1 = *(const float4*)(sz + c0 + 4);
            #pragma unroll
            for (int r = 0; r < 4; r++) {
                acc[r][0] = z0.x; acc[r][1] = z0.y; acc[r][2] = z0.z; acc[r][3] = z0.w;
                acc[r][4] = z1.x; acc[r][5] = z1.y; acc[r][6] = z1.z; acc[r][7] = z1.w;
            }
        }

        #pragma unroll 1
        for (int k0 = 0; k0 < DD; k0 += 4) {
            float ya[4][4];
            #pragma unroll
            for (int r = 0; r < 4; r++) {
                float4 v = *(const float4*)(sy + (r0 + r)*DD + k0);   // warp broadcast
                ya[r][0] = v.x; ya[r][1] = v.y; ya[r][2] = v.z; ya[r][3] = v.w;
            }
            float4 w0[4], w1[4];
            #pragma unroll
            for (int kk = 0; kk < 4; kk++) {
                w0[kk] = *(const float4*)(sW1 + (k0 + kk)*HH + c0);
                w1[kk] = *(const float4*)(sW1 + (k0 + kk)*HH + c0 + 4);
            }
            #pragma unroll
            for (int r = 0; r < 4; r++) {
                #pragma unroll
                for (int kk = 0; kk < 4; kk++) {
                    const float yk = ya[r][kk];
                    acc[r][0] += yk * w0[kk].x;
                    acc[r][1] += yk * w0[kk].y;
                    acc[r][2] += yk * w0[kk].z;
                    acc[r][3] += yk * w0[kk].w;
                    acc[r][4] += yk * w1[kk].x;
                    acc[r][5] += yk * w1[kk].y;
                    acc[r][6] += yk * w1[kk].z;
                    acc[r][7] += yk * w1[kk].w;
                }
            }
        }

        #pragma unroll
        for (int r = 0; r < 4; r++) {
            float4 o0, o1;
            o0.x = tanh_ap(acc[r][0]); o0.y = tanh_ap(acc[r][1]);
            o0.z = tanh_ap(acc[r][2]); o0.w = tanh_ap(acc[r][3]);
            o1.x = tanh_ap(acc[r][4]); o1.y = tanh_ap(acc[r][5]);
            o1.z = tanh_ap(acc[r][6]); o1.w = tanh_ap(acc[r][7]);
            *(float4*)(sh + (r0 + r)*HPAD + c0)     = o0;
            *(float4*)(sh + (r0 + r)*HPAD + c0 + 4) = o1;
        }
    }
    __syncthreads();

    // =========== Divergence: div_r = sum_j (1 - h_rj^2) * s_j ===========
    {
        const int r = tid >> 3;           // 0..63
        const int q = tid & 7;            // eighth of hidden dim (32 j's)
        const float* hp = sh + r*HPAD + q*32;
        const float* sp = ss + q*32;
        float dv = 0.f;
        #pragma unroll
        for (int j = 0; j < 32; j += 4) {
            float4 hv = *(const float4*)(hp + j);
            float4 sv = *(const float4*)(sp + j);
            dv += (1.f - hv.x*hv.x) * sv.x;
            dv += (1.f - hv.y*hv.y) * sv.y;
            dv += (1.f - hv.z*hv.z) * sv.z;
            dv += (1.f - hv.w*hv.w) * sv.w;
        }
        dv += __shfl_xor_sync(0xffffffffu, dv, 1);
        dv += __shfl_xor_sync(0xffffffffu, dv, 2);
        dv += __shfl_xor_sync(0xffffffffu, dv, 4);
        if (q == 0)
            out[(size_t)(blockIdx.x*ROWS + r)*(DD+1) + DD] = -dv;
    }

    // =========== Phase 2: DY = H @ W2 + b2, 2x4 tile / thread ===========
    {
        const int rt = tid >> 4;          // 0..31 -> 2 rows
        const int ct = tid & 15;          // 0..15 -> 4 cols
        const int r0 = rt * 2, c0 = ct * 4;

        float acc[2][4];
        #pragma unroll
        for (int r = 0; r < 2; r++)
            #pragma unroll
            for (int c = 0; c < 4; c++) acc[r][c] = 0.f;

        #pragma unroll 2
        for (int k0 = 0; k0 < HH; k0 += 4) {
            float ha[2][4];
            #pragma unroll
            for (int r = 0; r < 2; r++) {
                float4 v = *(const float4*)(sh + (r0 + r)*HPAD + k0);
                ha[r][0] = v.x; ha[r][1] = v.y; ha[r][2] = v.z; ha[r][3] = v.w;
            }
            float4 ww[4];
            #pragma unroll
            for (int kk = 0; kk < 4; kk++)
                ww[kk] = *(const float4*)(sW2 + (k0 + kk)*DD + c0);
            #pragma unroll
            for (int r = 0; r < 2; r++) {
                #pragma unroll
                for (int kk = 0; kk < 4; kk++) {
                    const float hk = ha[r][kk];
                    acc[r][0] += hk * ww[kk].x;
                    acc[r][1] += hk * ww[kk].y;
                    acc[r][2] += hk * ww[kk].z;
                    acc[r][3] += hk * ww[kk].w;
                }
            }
        }

        const float4 bb = *(const float4*)(sb2 + c0);
        #pragma unroll
        for (int r = 0; r < 2; r++) {
            float* op = out + (size_t)(blockIdx.x*ROWS + r0 + r)*(DD+1) + c0;
            op[0] = acc[r][0] + bb.x;
            op[1] = acc[r][1] + bb.y;
            op[2] = acc[r][2] + bb.z;
            op[3] = acc[r][3] + bb.w;
        }
    }
}

extern "C" void kernel_launch(void* const* d_in, const int* in_sizes, int n_in,
                              void* d_out, int out_size) {
    const float* t  = (const float*)d_in[0];
    const float* y  = (const float*)d_in[1];
    const float* W1 = (const float*)d_in[2];
    const float* b1 = (const float*)d_in[3];
    const float* wt = (const float*)d_in[4];
    const float* W2 = (const float*)d_in[5];
    const float* b2 = (const float*)d_in[6];
    float* out = (float*)d_out;

    const int n = in_sizes[1] / DD;          // 8192
    const int blocks = n / ROWS;             // 128

    cudaFuncSetAttribute(ode_kernel,
                         cudaFuncAttributeMaxDynamicSharedMemorySize, SMEM_BYTES);
    ode_kernel<<<blocks, THREADS, SMEM_BYTES>>>(t, y, W1, b1, wt, W2, b2, out);
}

// round 9
// speedup vs baseline: 1.4375x; 1.4375x over previous
#include <cuda_runtime.h>
#include <cuda_bf16.h>
#include <cstdint>

#define DD 64
#define HH 256
#define ROWS 64            // rows per CTA
#define THREADS 128        // 4 warps x 16-row stripes

// smem: bf16 operand tiles, [row][k] with hi|lo split along k, padded strides
// stride units are bf16 elements; byte strides 272 / 272 / 1040 (all %16==0,
// row-start bank = 4*row -> ldmatrix conflict-free)
#define YSTR  136          // Y:   64 rows x (64 hi | 64 lo)
#define W1STR 136          // W1t: 256 rows x (64 hi | 64 lo)
#define W2STR 520          // W2t: 64 rows x (256 hi | 256 lo)

#define SM_Y   0
#define SM_W1  (SM_Y  + ROWS * YSTR * 2)          // 17408
#define SM_W2  (SM_W1 + HH * W1STR * 2)           // 17408+69632 = 87040
#define SM_Z   (SM_W2 + DD * W2STR * 2)           // +66560 = 153600
#define SM_S   (SM_Z + HH * 4)
#define SM_B2  (SM_S + HH * 4)
#define SMEM_TOTAL (SM_B2 + DD * 4 + 16)

__device__ __forceinline__ uint32_t smem_u32(const void* p) {
    uint32_t a;
    asm("{ .reg .u64 t; cvta.to.shared.u64 t, %1; cvt.u32.u64 %0, t; }" : "=r"(a) : "l"(p));
    return a;
}
__device__ __forceinline__ float tanh_ap(float x) {
    float r; asm("tanh.approx.f32 %0, %1;" : "=f"(r) : "f"(x)); return r;
}
__device__ __forceinline__ uint32_t packbf(float lo, float hi) {
    __nv_bfloat162 v = __floats2bfloat162_rn(lo, hi);   // .x = lo (low 16 bits)
    return *(uint32_t*)&v;
}
__device__ __forceinline__ void mma_bf16(float c[4], const uint32_t a[4], const uint32_t b[2]) {
    asm volatile("mma.sync.aligned.m16n8k16.row.col.f32.bf16.bf16.f32 "
        "{%0,%1,%2,%3}, {%4,%5,%6,%7}, {%8,%9}, {%0,%1,%2,%3};"
        : "+f"(c[0]), "+f"(c[1]), "+f"(c[2]), "+f"(c[3])
        : "r"(a[0]), "r"(a[1]), "r"(a[2]), "r"(a[3]), "r"(b[0]), "r"(b[1]));
}
#define LDM4(R, addr) asm volatile( \
    "ldmatrix.sync.aligned.m8n8.x4.shared.b16 {%0,%1,%2,%3}, [%4];" \
    : "=r"((R)[0]), "=r"((R)[1]), "=r"((R)[2]), "=r"((R)[3]) : "r"(addr))
#define LDM2(R, addr) asm volatile( \
    "ldmatrix.sync.aligned.m8n8.x2.shared.b16 {%0,%1}, [%2];" \
    : "=r"((R)[0]), "=r"((R)[1]) : "r"(addr))

__global__ __launch_bounds__(THREADS, 1)
void ode_mma(const float* __restrict__ tptr, const float* __restrict__ y,
             const float* __restrict__ W1, const float* __restrict__ b1,
             const float* __restrict__ wt, const float* __restrict__ W2,
             const float* __restrict__ b2, float* __restrict__ out)
{
    extern __shared__ char smc[];
    __nv_bfloat16* sY  = (__nv_bfloat16*)(smc + SM_Y);
    __nv_bfloat16* sW1 = (__nv_bfloat16*)(smc + SM_W1);
    __nv_bfloat16* sW2 = (__nv_bfloat16*)(smc + SM_W2);
    float* sz  = (float*)(smc + SM_Z);
    float* ss  = (float*)(smc + SM_S);
    float* sbb = (float*)(smc + SM_B2);

    const uint32_t sbase = smem_u32(smc);
    const int tid  = threadIdx.x;
    const int lane = tid & 31;
    const int warp = tid >> 5;

    // ============ prologue: stage bf16 hi/lo operands ============
    {   // Y tile [64][64] -> sY[r][d | 64+d]
        const float* yb = y + (size_t)blockIdx.x * ROWS * DD;
        for (int idx = tid; idx < ROWS * DD; idx += THREADS) {
            int r = idx >> 6, d = idx & 63;
            float v = yb[idx];
            __nv_bfloat16 h = __float2bfloat16(v);
            sY[r * YSTR + d]      = h;
            sY[r * YSTR + 64 + d] = __float2bfloat16(v - __bfloat162float(h));
        }
        // W1 [d][j] -> sW1[j][d | 64+d]
        for (int idx = tid; idx < DD * HH; idx += THREADS) {
            int d = idx >> 8, j = idx & 255;
            float v = W1[idx];
            __nv_bfloat16 h = __float2bfloat16(v);
            sW1[j * W1STR + d]      = h;
            sW1[j * W1STR + 64 + d] = __float2bfloat16(v - __bfloat162float(h));
        }
        // W2 [hr][n] -> sW2[n][hr | 256+hr]
        for (int idx = tid; idx < HH * DD; idx += THREADS) {
            int hr = idx >> 6, n = idx & 63;
            float v = W2[idx];
            __nv_bfloat16 h = __float2bfloat16(v);
            sW2[n * W2STR + hr]       = h;
            sW2[n * W2STR + 256 + hr] = __float2bfloat16(v - __bfloat162float(h));
        }
        const float tv = tptr[0];
        for (int j = tid; j < HH; j += THREADS) {
            sz[j] = tv * wt[j] + b1[j];
            float s = 0.f;
            #pragma unroll
            for (int d = 0; d < DD; d++)
                s += W1[d * HH + j] * W2[j * DD + d];
            ss[j] = s;
        }
        if (tid < DD) sbb[tid] = b2[tid];
    }
    __syncthreads();

    // ============ per-warp 16-row stripe ============
    const int r0 = warp * 16;

    // Y A-fragments (resident): 4 k16-chunks, hi+lo
    uint32_t yhi[4][4], ylo[4][4];
    {
        const int arow = r0 + (lane & 7) + ((lane >> 3) & 1) * 8;
        const int acol = ((lane >> 4) & 1) * 8;
        const uint32_t abase = sbase + SM_Y + (uint32_t)arow * (YSTR * 2);
        #pragma unroll
        for (int kk = 0; kk < 4; kk++) {
            LDM4(yhi[kk], abase + (uint32_t)(kk * 16 + acol) * 2);
            LDM4(ylo[kk], abase + (uint32_t)(64 + kk * 16 + acol) * 2);
        }
    }

    float acc2[8][4];
    #pragma unroll
    for (int t = 0; t < 8; t++)
        #pragma unroll
        for (int i = 0; i < 4; i++) acc2[t][i] = 0.f;
    float dvlo = 0.f, dvhi = 0.f;

    const int qq = (lane & 3) * 2;              // col-pair within fragment
    const int brow8 = (lane & 7);
    const int bk8 = ((lane >> 3) & 1) * 8;

    #pragma unroll 1
    for (int jj = 0; jj < 16; jj++) {
        // ---- GEMM1 for 16 hidden units: two n8 fragments ----
        float cf[2][4];
        #pragma unroll
        for (int p = 0; p < 2; p++) {
            const int j0p = jj * 16 + p * 8;
            float2 zz = *(const float2*)(sz + j0p + qq);
            cf[p][0] = zz.x; cf[p][1] = zz.y; cf[p][2] = zz.x; cf[p][3] = zz.y;

            const uint32_t bbase = sbase + SM_W1 + (uint32_t)(j0p + brow8) * (W1STR * 2);
            #pragma unroll
            for (int kk = 0; kk < 4; kk++) {
                uint32_t bhi[2], blo[2];
                LDM2(bhi, bbase + (uint32_t)(kk * 16 + bk8) * 2);
                LDM2(blo, bbase + (uint32_t)(64 + kk * 16 + bk8) * 2);
                mma_bf16(cf[p], yhi[kk], bhi);
                mma_bf16(cf[p], ylo[kk], bhi);
                mma_bf16(cf[p], yhi[kk], blo);
            }
        }

        // ---- epilogue-1: tanh, divergence, split -> A2 fragments ----
        uint32_t ahi[4], alo[4];
        #pragma unroll
        for (int p = 0; p < 2; p++) {
            float2 sv = *(const float2*)(ss + jj * 16 + p * 8 + qq);
            float h0 = tanh_ap(cf[p][0]);
            float h1 = tanh_ap(cf[p][1]);
            float h2 = tanh_ap(cf[p][2]);
            float h3 = tanh_ap(cf[p][3]);
            dvlo += (1.f - h0 * h0) * sv.x + (1.f - h1 * h1) * sv.y;
            dvhi += (1.f - h2 * h2) * sv.x + (1.f - h3 * h3) * sv.y;
            float q0 = h0 - __bfloat162float(__float2bfloat16(h0));
            float q1 = h1 - __bfloat162float(__float2bfloat16(h1));
            float q2 = h2 - __bfloat162float(__float2bfloat16(h2));
            float q3 = h3 - __bfloat162float(__float2bfloat16(h3));
            ahi[p * 2 + 0] = packbf(h0, h1);
            ahi[p * 2 + 1] = packbf(h2, h3);
            alo[p * 2 + 0] = packbf(q0, q1);
            alo[p * 2 + 1] = packbf(q2, q3);
        }
        // reorder: a0,a1 from p0 (k 0-7), a2,a3 from p1 (k 8-15)
        uint32_t Ah[4] = { ahi[0], ahi[1], ahi[2], ahi[3] };
        uint32_t Al[4] = { alo[0], alo[1], alo[2], alo[3] };

        // ---- GEMM2 accumulate over this k16 chunk ----
        #pragma unroll
        for (int t = 0; t < 8; t++) {
            const uint32_t b2base = sbase + SM_W2 + (uint32_t)(t * 8 + brow8) * (W2STR * 2);
            uint32_t bh[2], bl[2];
            LDM2(bh, b2base + (uint32_t)(jj * 16 + bk8) * 2);
            LDM2(bl, b2base + (uint32_t)(256 + jj * 16 + bk8) * 2);
            mma_bf16(acc2[t], Ah, bh);
            mma_bf16(acc2[t], Al, bh);
            mma_bf16(acc2[t], Ah, bl);
        }
    }

    // ============ output ============
    const int rowA = blockIdx.x * ROWS + r0 + (lane >> 2);
    float* opA = out + (size_t)rowA * (DD + 1);
    float* opB = out + (size_t)(rowA + 8) * (DD + 1);
    #pragma unroll
    for (int t = 0; t < 8; t++) {
        const int n = t * 8 + qq;
        float2 bb = *(const float2*)(sbb + n);
        opA[n]     = acc2[t][0] + bb.x;
        opA[n + 1] = acc2[t][1] + bb.y;
        opB[n]     = acc2[t][2] + bb.x;
        opB[n + 1] = acc2[t][3] + bb.y;
    }
    // divergence: reduce over the 4 lanes sharing a row
    dvlo += __shfl_xor_sync(0xffffffffu, dvlo, 1);
    dvlo += __shfl_xor_sync(0xffffffffu, dvlo, 2);
    dvhi += __shfl_xor_sync(0xffffffffu, dvhi, 1);
    dvhi += __shfl_xor_sync(0xffffffffu, dvhi, 2);
    if ((lane & 3) == 0) {
        opA[DD] = -dvlo;
        opB[DD] = -dvhi;
    }
}

extern "C" void kernel_launch(void* const* d_in, const int* in_sizes, int n_in,
                              void* d_out, int out_size) {
    const float* t  = (const float*)d_in[0];
    const float* y  = (const float*)d_in[1];
    const float* W1 = (const float*)d_in[2];
    const float* b1 = (const float*)d_in[3];
    const float* wt = (const float*)d_in[4];
    const float* W2 = (const float*)d_in[5];
    const float* b2 = (const float*)d_in[6];
    float* out = (float*)d_out;

    const int n = in_sizes[1] / DD;          // 8192
    const int blocks = n / ROWS;             // 128

    cudaFuncSetAttribute(ode_mma,
                         cudaFuncAttributeMaxDynamicSharedMemorySize, SMEM_TOTAL);
    ode_mma<<<blocks, THREADS, SMEM_TOTAL>>>(t, y, W1, b1, wt, W2, b2, out);
}

// round 10
// speedup vs baseline: 1.7063x; 1.1870x over previous
#include <cuda_runtime.h>
#include <cuda_bf16.h>
#include <cstdint>

#define DD 64
#define HH 256
#define ROWS 64            // rows per CTA
#define THREADS 256        // 8 warps = 4 row-stripes x 2 jj-parts

// smem bf16 operand tiles, [row][k] hi|lo split along k, padded strides
#define YSTR  136
#define W1STR 136
#define W2STR 520

#define SM_Y   0
#define SM_W1  (SM_Y  + ROWS * YSTR * 2)          // 17408
#define SM_W2  (SM_W1 + HH * W1STR * 2)           // 87040
#define SM_Z   (SM_W2 + DD * W2STR * 2)           // 153600
#define SM_S   (SM_Z + HH * 4)
#define SM_B2  (SM_S + HH * 4)
#define SMEM_TOTAL (SM_B2 + DD * 4 + 16)

// post-mainloop reuse of [SM_Y..) : partial accumulators + div partials
#define SM_P   0           // float [2][64][64] = 32768 B
#define SM_DV  32768       // float [2][64]     = 512 B   (< SM_W2, safe)

__device__ __forceinline__ uint32_t smem_u32(const void* p) {
    uint32_t a;
    asm("{ .reg .u64 t; cvta.to.shared.u64 t, %1; cvt.u32.u64 %0, t; }" : "=r"(a) : "l"(p));
    return a;
}
__device__ __forceinline__ float tanh_ap(float x) {
    float r; asm("tanh.approx.f32 %0, %1;" : "=f"(r) : "f"(x)); return r;
}
__device__ __forceinline__ uint32_t packbf(float lo, float hi) {
    __nv_bfloat162 v = __floats2bfloat162_rn(lo, hi);
    return *(uint32_t*)&v;
}
__device__ __forceinline__ void mma_bf16(float c[4], const uint32_t a[4], const uint32_t b[2]) {
    asm volatile("mma.sync.aligned.m16n8k16.row.col.f32.bf16.bf16.f32 "
        "{%0,%1,%2,%3}, {%4,%5,%6,%7}, {%8,%9}, {%0,%1,%2,%3};"
        : "+f"(c[0]), "+f"(c[1]), "+f"(c[2]), "+f"(c[3])
        : "r"(a[0]), "r"(a[1]), "r"(a[2]), "r"(a[3]), "r"(b[0]), "r"(b[1]));
}
#define LDM4(R, addr) asm volatile( \
    "ldmatrix.sync.aligned.m8n8.x4.shared.b16 {%0,%1,%2,%3}, [%4];" \
    : "=r"((R)[0]), "=r"((R)[1]), "=r"((R)[2]), "=r"((R)[3]) : "r"(addr))
#define LDM2(R, addr) asm volatile( \
    "ldmatrix.sync.aligned.m8n8.x2.shared.b16 {%0,%1}, [%2];" \
    : "=r"((R)[0]), "=r"((R)[1]) : "r"(addr))

__global__ __launch_bounds__(THREADS, 1)
void ode_mma(const float* __restrict__ tptr, const float* __restrict__ y,
             const float* __restrict__ W1, const float* __restrict__ b1,
             const float* __restrict__ wt, const float* __restrict__ W2,
             const float* __restrict__ b2, float* __restrict__ out)
{
    extern __shared__ char smc[];
    __nv_bfloat16* sY  = (__nv_bfloat16*)(smc + SM_Y);
    __nv_bfloat16* sW1 = (__nv_bfloat16*)(smc + SM_W1);
    __nv_bfloat16* sW2 = (__nv_bfloat16*)(smc + SM_W2);
    float* sz  = (float*)(smc + SM_Z);
    float* ss  = (float*)(smc + SM_S);
    float* sbb = (float*)(smc + SM_B2);

    const uint32_t sbase = smem_u32(smc);
    const int tid  = threadIdx.x;
    const int lane = tid & 31;
    const int warp = tid >> 5;
    const int stripe = warp & 3;          // 16-row stripe
    const int part   = warp >> 2;         // jj half (0 or 1)

    // ============ prologue: stage bf16 hi/lo operands ============
    {
        const float* yb = y + (size_t)blockIdx.x * ROWS * DD;
        for (int idx = tid; idx < ROWS * DD; idx += THREADS) {
            int r = idx >> 6, d = idx & 63;
            float v = yb[idx];
            __nv_bfloat16 h = __float2bfloat16(v);
            sY[r * YSTR + d]      = h;
            sY[r * YSTR + 64 + d] = __float2bfloat16(v - __bfloat162float(h));
        }
        for (int idx = tid; idx < DD * HH; idx += THREADS) {
            int d = idx >> 8, j = idx & 255;
            float v = W1[idx];
            __nv_bfloat16 h = __float2bfloat16(v);
            sW1[j * W1STR + d]      = h;
            sW1[j * W1STR + 64 + d] = __float2bfloat16(v - __bfloat162float(h));
        }
        for (int idx = tid; idx < HH * DD; idx += THREADS) {
            int hr = idx >> 6, n = idx & 63;
            float v = W2[idx];
            __nv_bfloat16 h = __float2bfloat16(v);
            sW2[n * W2STR + hr]       = h;
            sW2[n * W2STR + 256 + hr] = __float2bfloat16(v - __bfloat162float(h));
        }
        const float tv = tptr[0];
        for (int j = tid; j < HH; j += THREADS) {
            sz[j] = tv * wt[j] + b1[j];
            float s = 0.f;
            #pragma unroll
            for (int d = 0; d < DD; d++)
                s += W1[d * HH + j] * W2[j * DD + d];
            ss[j] = s;
        }
        if (tid < DD) sbb[tid] = b2[tid];
    }
    __syncthreads();

    // ============ per-warp: 16-row stripe, half the hidden dim ============
    const int r0 = stripe * 16;

    uint32_t yhi[4][4], ylo[4][4];
    {
        const int arow = r0 + (lane & 7) + ((lane >> 3) & 1) * 8;
        const int acol = ((lane >> 4) & 1) * 8;
        const uint32_t abase = sbase + SM_Y + (uint32_t)arow * (YSTR * 2);
        #pragma unroll
        for (int kk = 0; kk < 4; kk++) {
            LDM4(yhi[kk], abase + (uint32_t)(kk * 16 + acol) * 2);
            LDM4(ylo[kk], abase + (uint32_t)(64 + kk * 16 + acol) * 2);
        }
    }

    float acc2[8][4];
    #pragma unroll
    for (int t = 0; t < 8; t++)
        #pragma unroll
        for (int i = 0; i < 4; i++) acc2[t][i] = 0.f;
    float dvlo = 0.f, dvhi = 0.f;

    const int qq = (lane & 3) * 2;
    const int brow8 = (lane & 7);
    const int bk8 = ((lane >> 3) & 1) * 8;

    const int jjBeg = part * 8, jjEnd = jjBeg + 8;
    #pragma unroll 1
    for (int jj = jjBeg; jj < jjEnd; jj++) {
        // ---- GEMM1: 3 independent accumulator chains per n8 fragment ----
        float cfA[2][4], cfB[2][4], cfC[2][4];
        #pragma unroll
        for (int p = 0; p < 2; p++) {
            const int j0p = jj * 16 + p * 8;
            float2 zz = *(const float2*)(sz + j0p + qq);
            cfA[p][0] = zz.x; cfA[p][1] = zz.y; cfA[p][2] = zz.x; cfA[p][3] = zz.y;
            #pragma unroll
            for (int i = 0; i < 4; i++) { cfB[p][i] = 0.f; cfC[p][i] = 0.f; }

            const uint32_t bbase = sbase + SM_W1 + (uint32_t)(j0p + brow8) * (W1STR * 2);
            #pragma unroll
            for (int kk = 0; kk < 4; kk++) {
                uint32_t bhi[2], blo[2];
                LDM2(bhi, bbase + (uint32_t)(kk * 16 + bk8) * 2);
                LDM2(blo, bbase + (uint32_t)(64 + kk * 16 + bk8) * 2);
                mma_bf16(cfA[p], yhi[kk], bhi);   // hi*hi
                mma_bf16(cfB[p], ylo[kk], bhi);   // lo*hi
                mma_bf16(cfC[p], yhi[kk], blo);   // hi*lo
            }
        }

        // ---- epilogue-1: tanh, divergence, split -> A2 fragments ----
        uint32_t Ah[4], Al[4];
        #pragma unroll
        for (int p = 0; p < 2; p++) {
            float2 sv = *(const float2*)(ss + jj * 16 + p * 8 + qq);
            float c0 = (cfA[p][0] + cfB[p][0]) + cfC[p][0];
            float c1 = (cfA[p][1] + cfB[p][1]) + cfC[p][1];
            float c2 = (cfA[p][2] + cfB[p][2]) + cfC[p][2];
            float c3 = (cfA[p][3] + cfB[p][3]) + cfC[p][3];
            float h0 = tanh_ap(c0), h1 = tanh_ap(c1);
            float h2 = tanh_ap(c2), h3 = tanh_ap(c3);
            dvlo += (1.f - h0 * h0) * sv.x + (1.f - h1 * h1) * sv.y;
            dvhi += (1.f - h2 * h2) * sv.x + (1.f - h3 * h3) * sv.y;
            float q0 = h0 - __bfloat162float(__float2bfloat16(h0));
            float q1 = h1 - __bfloat162float(__float2bfloat16(h1));
            float q2 = h2 - __bfloat162float(__float2bfloat16(h2));
            float q3 = h3 - __bfloat162float(__float2bfloat16(h3));
            Ah[p * 2 + 0] = packbf(h0, h1);
            Ah[p * 2 + 1] = packbf(h2, h3);
            Al[p * 2 + 0] = packbf(q0, q1);
            Al[p * 2 + 1] = packbf(q2, q3);
        }

        // ---- GEMM2: 8 independent accumulator chains ----
        #pragma unroll
        for (int t = 0; t < 8; t++) {
            const uint32_t b2base = sbase + SM_W2 + (uint32_t)(t * 8 + brow8) * (W2STR * 2);
            uint32_t bh[2], bl[2];
            LDM2(bh, b2base + (uint32_t)(jj * 16 + bk8) * 2);
            LDM2(bl, b2base + (uint32_t)(256 + jj * 16 + bk8) * 2);
            mma_bf16(acc2[t], Ah, bh);
            mma_bf16(acc2[t], Al, bh);
            mma_bf16(acc2[t], Ah, bl);
        }
    }

    // ============ combine the 2 jj-halves via smem ============
    __syncthreads();                       // all warps done reading Y/W1/W2
    {
        float* sP  = (float*)(smc + SM_P);   // [2][64][64]
        float* sDv = (float*)(smc + SM_DV);  // [2][64]
        const int rA = r0 + (lane >> 2);
        const int rB = rA + 8;
        float* pA = sP + ((size_t)part * ROWS + rA) * 64 + qq;
        float* pB = sP + ((size_t)part * ROWS + rB) * 64 + qq;
        #pragma unroll
        for (int t = 0; t < 8; t++) {
            *(float2*)(pA + t * 8) = make_float2(acc2[t][0], acc2[t][1]);
            *(float2*)(pB + t * 8) = make_float2(acc2[t][2], acc2[t][3]);
        }
        dvlo += __shfl_xor_sync(0xffffffffu, dvlo, 1);
        dvlo += __shfl_xor_sync(0xffffffffu, dvlo, 2);
        dvhi += __shfl_xor_sync(0xffffffffu, dvhi, 1);
        dvhi += __shfl_xor_sync(0xffffffffu, dvhi, 2);
        if ((lane & 3) == 0) {
            sDv[part * ROWS + rA] = dvlo;
            sDv[part * ROWS + rB] = dvhi;
        }
    }
    __syncthreads();

    // ============ final: sum partials + b2 -> out ============
    {
        const float* sP  = (const float*)(smc + SM_P);
        const float* sDv = (const float*)(smc + SM_DV);
        const int r  = tid >> 2;             // 0..63
        const int c0 = (tid & 3) * 16;
        float* op = out + (size_t)(blockIdx.x * ROWS + r) * (DD + 1);
        #pragma unroll
        for (int i = 0; i < 4; i++) {
            float4 a = *(const float4*)(sP + (size_t)r * 64 + c0 + i * 4);
            float4 b = *(const float4*)(sP + (size_t)(ROWS + r) * 64 + c0 + i * 4);
            float4 bb = *(const float4*)(sbb + c0 + i * 4);
            op[c0 + i * 4 + 0] = a.x + b.x + bb.x;
            op[c0 + i * 4 + 1] = a.y + b.y + bb.y;
            op[c0 + i * 4 + 2] = a.z + b.z + bb.z;
            op[c0 + i * 4 + 3] = a.w + b.w + bb.w;
        }
        if ((tid & 3) == 0)
            op[DD] = -(sDv[r] + sDv[ROWS + r]);
    }
}

extern "C" void kernel_launch(void* const* d_in, const int* in_sizes, int n_in,
                              void* d_out, int out_size) {
    const float* t  = (const float*)d_in[0];
    const float* y  = (const float*)d_in[1];
    const float* W1 = (const float*)d_in[2];
    const float* b1 = (const float*)d_in[3];
    const float* wt = (const float*)d_in[4];
    const float* W2 = (const float*)d_in[5];
    const float* b2 = (const float*)d_in[6];
    float* out = (float*)d_out;

    const int n = in_sizes[1] / DD;          // 8192
    const int blocks = n / ROWS;             // 128

    cudaFuncSetAttribute(ode_mma,
                         cudaFuncAttributeMaxDynamicSharedMemorySize, SMEM_TOTAL);
    ode_mma<<<blocks, THREADS, SMEM_TOTAL>>>(t, y, W1, b1, wt, W2, b2, out);
}

// round 11
// speedup vs baseline: 1.9823x; 1.1617x over previous
#include <cuda_runtime.h>
#include <cuda_bf16.h>
#include <cstdint>

#define DD 64
#define HH 256
#define ROWS 64            // rows per CTA
#define THREADS 512        // 16 warps = 4 row-stripes x 4 jj-parts

// padded bf16 strides (elements)
#define YSTR  136
#define W1STR 136
#define W2STR 520

#define W1IMG_BYTES (HH * W1STR * 2)   // 69632
#define W2IMG_BYTES (DD * W2STR * 2)   // 66560

#define SM_Y   0
#define SM_W1  (SM_Y  + ROWS * YSTR * 2)          // 17408
#define SM_W2  (SM_W1 + W1IMG_BYTES)              // 87040
#define SM_Z   (SM_W2 + W2IMG_BYTES)              // 153600
#define SM_S   (SM_Z + HH * 4)
#define SM_B2  (SM_S + HH * 4)
#define SMEM_TOTAL (SM_B2 + DD * 4 + 16)

// post-mainloop reuse of [SM_Y .. SM_W2): partials + div partials
#define SM_P   0           // float [4][64][64] = 65536 B
#define SM_DV  65536       // float [4][64]     = 1024 B  (< 87040, safe)

// ---- global scratch: weight images converted ONCE by prep kernel ----
__device__ __align__(16) unsigned char g_w1img[W1IMG_BYTES];
__device__ __align__(16) unsigned char g_w2img[W2IMG_BYTES];
__device__ __align__(16) float g_z[HH];
__device__ __align__(16) float g_s[HH];
__device__ __align__(16) float g_b2[DD];

__device__ __forceinline__ uint32_t smem_u32(const void* p) {
    uint32_t a;
    asm("{ .reg .u64 t; cvta.to.shared.u64 t, %1; cvt.u32.u64 %0, t; }" : "=r"(a) : "l"(p));
    return a;
}
__device__ __forceinline__ float tanh_ap(float x) {
    float r; asm("tanh.approx.f32 %0, %1;" : "=f"(r) : "f"(x)); return r;
}
__device__ __forceinline__ uint32_t packbf(float lo, float hi) {
    __nv_bfloat162 v = __floats2bfloat162_rn(lo, hi);
    return *(uint32_t*)&v;
}
__device__ __forceinline__ void mma_bf16(float c[4], const uint32_t a[4], const uint32_t b[2]) {
    asm volatile("mma.sync.aligned.m16n8k16.row.col.f32.bf16.bf16.f32 "
        "{%0,%1,%2,%3}, {%4,%5,%6,%7}, {%8,%9}, {%0,%1,%2,%3};"
        : "+f"(c[0]), "+f"(c[1]), "+f"(c[2]), "+f"(c[3])
        : "r"(a[0]), "r"(a[1]), "r"(a[2]), "r"(a[3]), "r"(b[0]), "r"(b[1]));
}
#define LDM4(R, addr) asm volatile( \
    "ldmatrix.sync.aligned.m8n8.x4.shared.b16 {%0,%1,%2,%3}, [%4];" \
    : "=r"((R)[0]), "=r"((R)[1]), "=r"((R)[2]), "=r"((R)[3]) : "r"(addr))
#define LDM2(R, addr) asm volatile( \
    "ldmatrix.sync.aligned.m8n8.x2.shared.b16 {%0,%1}, [%2];" \
    : "=r"((R)[0]), "=r"((R)[1]) : "r"(addr))

// ============ prep kernel: convert weights once ============
__global__ __launch_bounds__(256, 1)
void ode_prep(const float* __restrict__ tptr, const float* __restrict__ W1,
              const float* __restrict__ b1, const float* __restrict__ wt,
              const float* __restrict__ W2, const float* __restrict__ b2)
{
    const int gidx = blockIdx.x * 256 + threadIdx.x;   // 0..16383 (grid 64)
    __nv_bfloat16* w1i = (__nv_bfloat16*)g_w1img;
    __nv_bfloat16* w2i = (__nv_bfloat16*)g_w2img;
    {   // one W1 element per thread: [d][j] -> image[j][d | 64+d]
        int d = gidx >> 8, j = gidx & 255;
        float v = W1[gidx];
        __nv_bfloat16 h = __float2bfloat16(v);
        w1i[j * W1STR + d]      = h;
        w1i[j * W1STR + 64 + d] = __float2bfloat16(v - __bfloat162float(h));
    }
    {   // one W2 element per thread: [hr][n] -> image[n][hr | 256+hr]
        int hr = gidx >> 6, n = gidx & 63;
        float v = W2[gidx];
        __nv_bfloat16 h = __float2bfloat16(v);
        w2i[n * W2STR + hr]       = h;
        w2i[n * W2STR + 256 + hr] = __float2bfloat16(v - __bfloat162float(h));
    }
    if (gidx < HH) {
        g_z[gidx] = tptr[0] * wt[gidx] + b1[gidx];
        float s = 0.f;
        #pragma unroll
        for (int d = 0; d < DD; d++)
            s += W1[d * HH + gidx] * W2[gidx * DD + d];
        g_s[gidx] = s;
    }
    if (gidx < DD) g_b2[gidx] = b2[gidx];
}

// ============ main kernel ============
__global__ __launch_bounds__(THREADS, 1)
void ode_mma(const float* __restrict__ y, float* __restrict__ out)
{
    extern __shared__ char smc[];
    __nv_bfloat16* sY = (__nv_bfloat16*)(smc + SM_Y);
    float* sz  = (float*)(smc + SM_Z);
    float* ss  = (float*)(smc + SM_S);
    float* sbb = (float*)(smc + SM_B2);

    const uint32_t sbase = smem_u32(smc);
    const int tid  = threadIdx.x;
    const int lane = tid & 31;
    const int warp = tid >> 5;
    const int stripe = warp & 3;          // 16-row stripe
    const int part   = warp >> 2;         // jj quarter (0..3)

    // ---- prologue: flat copies of pre-converted images + per-CTA Y convert ----
    {
        const float4* s1 = (const float4*)g_w1img;
        float4* d1 = (float4*)(smc + SM_W1);
        #pragma unroll
        for (int i = tid; i < W1IMG_BYTES / 16; i += THREADS) d1[i] = s1[i];
        const float4* s2 = (const float4*)g_w2img;
        float4* d2 = (float4*)(smc + SM_W2);
        #pragma unroll
        for (int i = tid; i < W2IMG_BYTES / 16; i += THREADS) d2[i] = s2[i];
        if (tid < HH) { sz[tid] = g_z[tid]; ss[tid] = g_s[tid]; }
        if (tid < DD) sbb[tid] = g_b2[tid];

        const float* yb = y + (size_t)blockIdx.x * ROWS * DD;
        for (int idx = tid; idx < ROWS * DD; idx += THREADS) {
            int r = idx >> 6, d = idx & 63;
            float v = yb[idx];
            __nv_bfloat16 h = __float2bfloat16(v);
            sY[r * YSTR + d]      = h;
            sY[r * YSTR + 64 + d] = __float2bfloat16(v - __bfloat162float(h));
        }
    }
    __syncthreads();

    // ---- per-warp: 16-row stripe, quarter of hidden dim ----
    const int r0 = stripe * 16;

    uint32_t yhi[4][4], ylo[4][4];
    {
        const int arow = r0 + (lane & 7) + ((lane >> 3) & 1) * 8;
        const int acol = ((lane >> 4) & 1) * 8;
        const uint32_t abase = sbase + SM_Y + (uint32_t)arow * (YSTR * 2);
        #pragma unroll
        for (int kk = 0; kk < 4; kk++) {
            LDM4(yhi[kk], abase + (uint32_t)(kk * 16 + acol) * 2);
            LDM4(ylo[kk], abase + (uint32_t)(64 + kk * 16 + acol) * 2);
        }
    }

    float acc2[8][4];
    #pragma unroll
    for (int t = 0; t < 8; t++)
        #pragma unroll
        for (int i = 0; i < 4; i++) acc2[t][i] = 0.f;
    float dvlo = 0.f, dvhi = 0.f;

    const int qq = (lane & 3) * 2;
    const int brow8 = (lane & 7);
    const int bk8 = ((lane >> 3) & 1) * 8;

    const int jjBeg = part * 4, jjEnd = jjBeg + 4;
    #pragma unroll 1
    for (int jj = jjBeg; jj < jjEnd; jj++) {
        // GEMM1: 3 independent chains per n8 fragment
        float cfA[2][4], cfB[2][4], cfC[2][4];
        #pragma unroll
        for (int p = 0; p < 2; p++) {
            const int j0p = jj * 16 + p * 8;
            float2 zz = *(const float2*)(sz + j0p + qq);
            cfA[p][0] = zz.x; cfA[p][1] = zz.y; cfA[p][2] = zz.x; cfA[p][3] = zz.y;
            #pragma unroll
            for (int i = 0; i < 4; i++) { cfB[p][i] = 0.f; cfC[p][i] = 0.f; }

            const uint32_t bbase = sbase + SM_W1 + (uint32_t)(j0p + brow8) * (W1STR * 2);
            #pragma unroll
            for (int kk = 0; kk < 4; kk++) {
                uint32_t bhi[2], blo[2];
                LDM2(bhi, bbase + (uint32_t)(kk * 16 + bk8) * 2);
                LDM2(blo, bbase + (uint32_t)(64 + kk * 16 + bk8) * 2);
                mma_bf16(cfA[p], yhi[kk], bhi);
                mma_bf16(cfB[p], ylo[kk], bhi);
                mma_bf16(cfC[p], yhi[kk], blo);
            }
        }

        // epilogue-1: tanh + divergence + split -> A2 fragments
        uint32_t Ah[4], Al[4];
        #pragma unroll
        for (int p = 0; p < 2; p++) {
            float2 sv = *(const float2*)(ss + jj * 16 + p * 8 + qq);
            float c0 = (cfA[p][0] + cfB[p][0]) + cfC[p][0];
            float c1 = (cfA[p][1] + cfB[p][1]) + cfC[p][1];
            float c2 = (cfA[p][2] + cfB[p][2]) + cfC[p][2];
            float c3 = (cfA[p][3] + cfB[p][3]) + cfC[p][3];
            float h0 = tanh_ap(c0), h1 = tanh_ap(c1);
            float h2 = tanh_ap(c2), h3 = tanh_ap(c3);
            dvlo += (1.f - h0 * h0) * sv.x + (1.f - h1 * h1) * sv.y;
            dvhi += (1.f - h2 * h2) * sv.x + (1.f - h3 * h3) * sv.y;
            float q0 = h0 - __bfloat162float(__float2bfloat16(h0));
            float q1 = h1 - __bfloat162float(__float2bfloat16(h1));
            float q2 = h2 - __bfloat162float(__float2bfloat16(h2));
            float q3 = h3 - __bfloat162float(__float2bfloat16(h3));
            Ah[p * 2 + 0] = packbf(h0, h1);
            Ah[p * 2 + 1] = packbf(h2, h3);
            Al[p * 2 + 0] = packbf(q0, q1);
            Al[p * 2 + 1] = packbf(q2, q3);
        }

        // GEMM2: 8 independent chains
        #pragma unroll
        for (int t = 0; t < 8; t++) {
            const uint32_t b2base = sbase + SM_W2 + (uint32_t)(t * 8 + brow8) * (W2STR * 2);
            uint32_t bh[2], bl[2];
            LDM2(bh, b2base + (uint32_t)(jj * 16 + bk8) * 2);
            LDM2(bl, b2base + (uint32_t)(256 + jj * 16 + bk8) * 2);
            mma_bf16(acc2[t], Ah, bh);
            mma_bf16(acc2[t], Al, bh);
            mma_bf16(acc2[t], Ah, bl);
        }
    }

    // ---- combine the 4 jj-quarters via smem ----
    __syncthreads();
    {
        float* sP  = (float*)(smc + SM_P);   // [4][64][64]
        float* sDv = (float*)(smc + SM_DV);  // [4][64]
        const int rA = r0 + (lane >> 2);
        const int rB = rA + 8;
        float* pA = sP + ((size_t)part * ROWS + rA) * 64 + qq;
        float* pB = sP + ((size_t)part * ROWS + rB) * 64 + qq;
        #pragma unroll
        for (int t = 0; t < 8; t++) {
            *(float2*)(pA + t * 8) = make_float2(acc2[t][0], acc2[t][1]);
            *(float2*)(pB + t * 8) = make_float2(acc2[t][2], acc2[t][3]);
        }
        dvlo += __shfl_xor_sync(0xffffffffu, dvlo, 1);
        dvlo += __shfl_xor_sync(0xffffffffu, dvlo, 2);
        dvhi += __shfl_xor_sync(0xffffffffu, dvhi, 1);
        dvhi += __shfl_xor_sync(0xffffffffu, dvhi, 2);
        if ((lane & 3) == 0) {
            sDv[part * ROWS + rA] = dvlo;
            sDv[part * ROWS + rB] = dvhi;
        }
    }
    __syncthreads();

    // ---- final: sum 4 partials + b2 -> out ----
    {
        const float* sP  = (const float*)(smc + SM_P);
        const float* sDv = (const float*)(smc + SM_DV);
        const int r  = tid >> 3;             // 0..63
        const int c0 = (tid & 7) * 8;        // 8 cols per thread
        float* op = out + (size_t)(blockIdx.x * ROWS + r) * (DD + 1);
        #pragma unroll
        for (int i = 0; i < 2; i++) {
            const int c = c0 + i * 4;
            float4 a0 = *(const float4*)(sP + (size_t)(0 * ROWS + r) * 64 + c);
            float4 a1 = *(const float4*)(sP + (size_t)(1 * ROWS + r) * 64 + c);
            float4 a2 = *(const float4*)(sP + (size_t)(2 * ROWS + r) * 64 + c);
            float4 a3 = *(const float4*)(sP + (size_t)(3 * ROWS + r) * 64 + c);
            float4 bb = *(const float4*)(sbb + c);
            op[c + 0] = ((a0.x + a1.x) + (a2.x + a3.x)) + bb.x;
            op[c + 1] = ((a0.y + a1.y) + (a2.y + a3.y)) + bb.y;
            op[c + 2] = ((a0.z + a1.z) + (a2.z + a3.z)) + bb.z;
            op[c + 3] = ((a0.w + a1.w) + (a2.w + a3.w)) + bb.w;
        }
        if ((tid & 7) == 0)
            op[DD] = -(((sDv[r] + sDv[ROWS + r]) + (sDv[2 * ROWS + r] + sDv[3 * ROWS + r])));
    }
}

extern "C" void kernel_launch(void* const* d_in, const int* in_sizes, int n_in,
                              void* d_out, int out_size) {
    const float* t  = (const float*)d_in[0];
    const float* y  = (const float*)d_in[1];
    const float* W1 = (const float*)d_in[2];
    const float* b1 = (const float*)d_in[3];
    const float* wt = (const float*)d_in[4];
    const float* W2 = (const float*)d_in[5];
    const float* b2 = (const float*)d_in[6];
    float* out = (float*)d_out;

    const int n = in_sizes[1] / DD;          // 8192
    const int blocks = n / ROWS;             // 128

    ode_prep<<<64, 256>>>(t, W1, b1, wt, W2, b2);
    cudaFuncSetAttribute(ode_mma,
                         cudaFuncAttributeMaxDynamicSharedMemorySize, SMEM_TOTAL);
    ode_mma<<<blocks, THREADS, SMEM_TOTAL>>>(y, out);
}

// round 12
// speedup vs baseline: 2.8948x; 1.4603x over previous
#include <cuda_runtime.h>
#include <cuda_bf16.h>
#include <cstdint>

#define DD 64
#define HH 256
#define ROWS 64            // rows per CTA
#define THREADS 512        // 16 warps = 4 row-stripes x 4 jj-parts

// padded bf16 strides (elements)
#define YSTR  136
#define W1STR 136
#define W2STR 520

#define W1IMG_BYTES (HH * W1STR * 2)   // 69632
#define W2IMG_BYTES (DD * W2STR * 2)   // 66560

#define SM_Y   0
#define SM_W1  (SM_Y  + ROWS * YSTR * 2)          // 17408
#define SM_W2  (SM_W1 + W1IMG_BYTES)              // 87040
#define SM_Z   (SM_W2 + W2IMG_BYTES)              // 153600
#define SM_S   (SM_Z + HH * 4)
#define SM_B2  (SM_S + HH * 4)
#define SMEM_TOTAL (SM_B2 + DD * 4 + 16)

// post-mainloop reuse of [SM_Y .. SM_W2): partials + div partials
#define SM_P   0           // float [4][64][64] = 65536 B
#define SM_DV  65536       // float [4][64]     = 1024 B

__device__ __align__(16) unsigned char g_w1img[W1IMG_BYTES];
__device__ __align__(16) unsigned char g_w2img[W2IMG_BYTES];
__device__ __align__(16) float g_z[HH];
__device__ __align__(16) float g_s[HH];
__device__ __align__(16) float g_b2[DD];

__device__ __forceinline__ uint32_t smem_u32(const void* p) {
    uint32_t a;
    asm("{ .reg .u64 t; cvta.to.shared.u64 t, %1; cvt.u32.u64 %0, t; }" : "=r"(a) : "l"(p));
    return a;
}
__device__ __forceinline__ float tanh_ap(float x) {
    float r; asm("tanh.approx.f32 %0, %1;" : "=f"(r) : "f"(x)); return r;
}
__device__ __forceinline__ uint32_t packbf(float lo, float hi) {
    uint32_t r;
    asm("cvt.rn.bf16x2.f32 %0, %1, %2;" : "=r"(r) : "f"(hi), "f"(lo));
    return r;   // low 16 = lo operand
}
__device__ __forceinline__ void mma_bf16(float c[4], const uint32_t a[4], const uint32_t b[2]) {
    asm volatile("mma.sync.aligned.m16n8k16.row.col.f32.bf16.bf16.f32 "
        "{%0,%1,%2,%3}, {%4,%5,%6,%7}, {%8,%9}, {%0,%1,%2,%3};"
        : "+f"(c[0]), "+f"(c[1]), "+f"(c[2]), "+f"(c[3])
        : "r"(a[0]), "r"(a[1]), "r"(a[2]), "r"(a[3]), "r"(b[0]), "r"(b[1]));
}
#define LDM4(R, addr) asm volatile( \
    "ldmatrix.sync.aligned.m8n8.x4.shared.b16 {%0,%1,%2,%3}, [%4];" \
    : "=r"((R)[0]), "=r"((R)[1]), "=r"((R)[2]), "=r"((R)[3]) : "r"(addr))

// ============ prep kernel: convert weights once (fully parallel) ============
__global__ __launch_bounds__(256, 1)
void ode_prep(const float* __restrict__ tptr, const float* __restrict__ W1,
              const float* __restrict__ b1, const float* __restrict__ wt,
              const float* __restrict__ W2, const float* __restrict__ b2)
{
    const int gidx = blockIdx.x * 256 + threadIdx.x;   // 0..16383 (grid 64)
    __nv_bfloat16* w1i = (__nv_bfloat16*)g_w1img;
    __nv_bfloat16* w2i = (__nv_bfloat16*)g_w2img;
    {   // W1 [d][j] -> image[j][d | 64+d]
        int d = gidx >> 8, j = gidx & 255;
        float v = W1[gidx];
        __nv_bfloat16 h = __float2bfloat16(v);
        w1i[j * W1STR + d]      = h;
        w1i[j * W1STR + 64 + d] = __float2bfloat16(v - __bfloat162float(h));
    }
    {   // W2 [hr][n] -> image[n][hr | 256+hr]
        int hr = gidx >> 6, n = gidx & 63;
        float v = W2[gidx];
        __nv_bfloat16 h = __float2bfloat16(v);
        w2i[n * W2STR + hr]       = h;
        w2i[n * W2STR + 256 + hr] = __float2bfloat16(v - __bfloat162float(h));
    }
    // s_j: warp-per-j reduction (gidx < 8192 -> j = gidx>>5)
    if (gidx < 8192) {
        const int j = gidx >> 5, d = gidx & 31;
        float p = W1[d * HH + j] * W2[j * DD + d]
                + W1[(d + 32) * HH + j] * W2[j * DD + d + 32];
        p += __shfl_xor_sync(0xffffffffu, p, 1);
        p += __shfl_xor_sync(0xffffffffu, p, 2);
        p += __shfl_xor_sync(0xffffffffu, p, 4);
        p += __shfl_xor_sync(0xffffffffu, p, 8);
        p += __shfl_xor_sync(0xffffffffu, p, 16);
        if (d == 0) g_s[j] = p;
    }
    if (gidx < HH) g_z[gidx] = tptr[0] * wt[gidx] + b1[gidx];
    if (gidx < DD) g_b2[gidx] = b2[gidx];
}

// ============ main kernel ============
__global__ __launch_bounds__(THREADS, 1)
void ode_mma(const float* __restrict__ y, float* __restrict__ out)
{
    extern __shared__ char smc[];
    float* sz  = (float*)(smc + SM_Z);
    float* ss  = (float*)(smc + SM_S);
    float* sbb = (float*)(smc + SM_B2);

    const uint32_t sbase = smem_u32(smc);
    const int tid  = threadIdx.x;
    const int lane = tid & 31;
    const int warp = tid >> 5;
    const int stripe = warp & 3;          // 16-row stripe
    const int part   = warp >> 2;         // jj quarter (0..3)

    // ---- prologue: flat image copies + vectorized Y convert ----
    {
        const float4* s1 = (const float4*)g_w1img;
        float4* d1 = (float4*)(smc + SM_W1);
        #pragma unroll
        for (int i = tid; i < W1IMG_BYTES / 16; i += THREADS) d1[i] = s1[i];
        const float4* s2 = (const float4*)g_w2img;
        float4* d2 = (float4*)(smc + SM_W2);
        #pragma unroll
        for (int i = tid; i < W2IMG_BYTES / 16; i += THREADS) d2[i] = s2[i];
        if (tid < HH) { sz[tid] = g_z[tid]; ss[tid] = g_s[tid]; }
        if (tid < DD) sbb[tid] = g_b2[tid];

        // Y pairs: hi via truncation + byte_perm, lo via paired cvt
        const float2* yb = (const float2*)(y + (size_t)blockIdx.x * ROWS * DD);
        uint32_t* sy32 = (uint32_t*)(smc + SM_Y);
        #pragma unroll
        for (int i = tid; i < ROWS * DD / 2; i += THREADS) {
            const int r = i >> 5, dp = (i & 31);          // dp = d/2
            float2 v = yb[i];
            uint32_t u0 = __float_as_uint(v.x), u1 = __float_as_uint(v.y);
            uint32_t hi = __byte_perm(u0, u1, 0x7632);
            float l0 = v.x - __uint_as_float(u0 & 0xFFFF0000u);
            float l1 = v.y - __uint_as_float(u1 & 0xFFFF0000u);
            sy32[r * (YSTR / 2) + dp]      = hi;
            sy32[r * (YSTR / 2) + 32 + dp] = packbf(l0, l1);
        }
    }
    __syncthreads();

    // ---- per-warp: 16-row stripe, quarter of hidden dim ----
    const int r0 = stripe * 16;

    uint32_t yhi[4][4], ylo[4][4];
    {
        const int arow = r0 + (lane & 7) + ((lane >> 3) & 1) * 8;
        const int acol = ((lane >> 4) & 1) * 8;
        const uint32_t abase = sbase + SM_Y + (uint32_t)arow * (YSTR * 2);
        #pragma unroll
        for (int kk = 0; kk < 4; kk++) {
            LDM4(yhi[kk], abase + (uint32_t)(kk * 16 + acol) * 2);
            LDM4(ylo[kk], abase + (uint32_t)(64 + kk * 16 + acol) * 2);
        }
    }

    float acc2[8][4];
    #pragma unroll
    for (int t = 0; t < 8; t++)
        #pragma unroll
        for (int i = 0; i < 4; i++) acc2[t][i] = 0.f;
    float dvlo = 0.f, dvhi = 0.f;

    const int qq = (lane & 3) * 2;
    // hi|lo combined ldmatrix lane offsets (x4: lanes 16-31 -> lo matrices)
    const uint32_t w1lo_off = (uint32_t)(lane & 7) * (W1STR * 2)
        + (uint32_t)(((lane >> 3) & 1) * 8 + ((lane >> 4) & 1) * 64) * 2;
    const uint32_t w2lo_off = (uint32_t)(lane & 7) * (W2STR * 2)
        + (uint32_t)(((lane >> 3) & 1) * 8 + ((lane >> 4) & 1) * 256) * 2;

    const int jjBeg = part * 4, jjEnd = jjBeg + 4;
    #pragma unroll 1
    for (int jj = jjBeg; jj < jjEnd; jj++) {
        // ---- GEMM1: 3 independent chains per n8 fragment ----
        float cfA[2][4], cfB[2][4], cfC[2][4];
        #pragma unroll
        for (int p = 0; p < 2; p++) {
            const int j0p = jj * 16 + p * 8;
            float2 zz = *(const float2*)(sz + j0p + qq);
            cfA[p][0] = zz.x; cfA[p][1] = zz.y; cfA[p][2] = zz.x; cfA[p][3] = zz.y;
            #pragma unroll
            for (int i = 0; i < 4; i++) { cfB[p][i] = 0.f; cfC[p][i] = 0.f; }

            const uint32_t bbase = sbase + SM_W1 + (uint32_t)j0p * (W1STR * 2) + w1lo_off;
            #pragma unroll
            for (int kk = 0; kk < 4; kk++) {
                uint32_t bf[4];                      // [0:2)=hi, [2:4)=lo
                LDM4(bf, bbase + (uint32_t)kk * 32);
                mma_bf16(cfA[p], yhi[kk], bf);       // hi*hi
                mma_bf16(cfB[p], ylo[kk], bf);       // lo*hi
                mma_bf16(cfC[p], yhi[kk], bf + 2);   // hi*lo
            }
        }

        // ---- epilogue-1: tanh + cheap truncation split ----
        uint32_t Ah[4], Al[4];
        float hv[2][4];
        #pragma unroll
        for (int p = 0; p < 2; p++) {
            float h0 = tanh_ap((cfA[p][0] + cfB[p][0]) + cfC[p][0]);
            float h1 = tanh_ap((cfA[p][1] + cfB[p][1]) + cfC[p][1]);
            float h2 = tanh_ap((cfA[p][2] + cfB[p][2]) + cfC[p][2]);
            float h3 = tanh_ap((cfA[p][3] + cfB[p][3]) + cfC[p][3]);
            hv[p][0] = h0; hv[p][1] = h1; hv[p][2] = h2; hv[p][3] = h3;
            uint32_t u0 = __float_as_uint(h0), u1 = __float_as_uint(h1);
            uint32_t u2 = __float_as_uint(h2), u3 = __float_as_uint(h3);
            Ah[p * 2 + 0] = __byte_perm(u0, u1, 0x7632);
            Ah[p * 2 + 1] = __byte_perm(u2, u3, 0x7632);
            Al[p * 2 + 0] = packbf(h0 - __uint_as_float(u0 & 0xFFFF0000u),
                                   h1 - __uint_as_float(u1 & 0xFFFF0000u));
            Al[p * 2 + 1] = packbf(h2 - __uint_as_float(u2 & 0xFFFF0000u),
                                   h3 - __uint_as_float(u3 & 0xFFFF0000u));
        }

        // ---- GEMM2: 8 independent chains (b-frags hi+lo in one LDM4) ----
        const uint32_t b2base = sbase + SM_W2 + (uint32_t)(jj * 16) * 2 + w2lo_off;
        #pragma unroll
        for (int t = 0; t < 8; t++) {
            uint32_t bf[4];
            LDM4(bf, b2base + (uint32_t)t * 8 * (W2STR * 2));
            mma_bf16(acc2[t], Ah, bf);
            mma_bf16(acc2[t], Al, bf);
            mma_bf16(acc2[t], Ah, bf + 2);
        }

        // ---- divergence FMAs (independent; fills MMA stalls) ----
        #pragma unroll
        for (int p = 0; p < 2; p++) {
            float2 sv = *(const float2*)(ss + jj * 16 + p * 8 + qq);
            dvlo += (1.f - hv[p][0] * hv[p][0]) * sv.x + (1.f - hv[p][1] * hv[p][1]) * sv.y;
            dvhi += (1.f - hv[p][2] * hv[p][2]) * sv.x + (1.f - hv[p][3] * hv[p][3]) * sv.y;
        }
    }

    // ---- combine the 4 jj-quarters via smem ----
    __syncthreads();
    {
        float* sP  = (float*)(smc + SM_P);   // [4][64][64]
        float* sDv = (float*)(smc + SM_DV);  // [4][64]
        const int rA = r0 + (lane >> 2);
        const int rB = rA + 8;
        float* pA = sP + ((size_t)part * ROWS + rA) * 64 + qq;
        float* pB = sP + ((size_t)part * ROWS + rB) * 64 + qq;
        #pragma unroll
        for (int t = 0; t < 8; t++) {
            *(float2*)(pA + t * 8) = make_float2(acc2[t][0], acc2[t][1]);
            *(float2*)(pB + t * 8) = make_float2(acc2[t][2], acc2[t][3]);
        }
        dvlo += __shfl_xor_sync(0xffffffffu, dvlo, 1);
        dvlo += __shfl_xor_sync(0xffffffffu, dvlo, 2);
        dvhi += __shfl_xor_sync(0xffffffffu, dvhi, 1);
        dvhi += __shfl_xor_sync(0xffffffffu, dvhi, 2);
        if ((lane & 3) == 0) {
            sDv[part * ROWS + rA] = dvlo;
            sDv[part * ROWS + rB] = dvhi;
        }
    }
    __syncthreads();

    // ---- final: sum 4 partials + b2 -> out ----
    {
        const float* sP  = (const float*)(smc + SM_P);
        const float* sDv = (const float*)(smc + SM_DV);
        const int r  = tid >> 3;             // 0..63
        const int c0 = (tid & 7) * 8;
        float* op = out + (size_t)(blockIdx.x * ROWS + r) * (DD + 1);
        #pragma unroll
        for (int i = 0; i < 2; i++) {
            const int c = c0 + i * 4;
            float4 a0 = *(const float4*)(sP + (size_t)(0 * ROWS + r) * 64 + c);
            float4 a1 = *(const float4*)(sP + (size_t)(1 * ROWS + r) * 64 + c);
            float4 a2 = *(const float4*)(sP + (size_t)(2 * ROWS + r) * 64 + c);
            float4 a3 = *(const float4*)(sP + (size_t)(3 * ROWS + r) * 64 + c);
            float4 bb = *(const float4*)(sbb + c);
            op[c + 0] = ((a0.x + a1.x) + (a2.x + a3.x)) + bb.x;
            op[c + 1] = ((a0.y + a1.y) + (a2.y + a3.y)) + bb.y;
            op[c + 2] = ((a0.z + a1.z) + (a2.z + a3.z)) + bb.z;
            op[c + 3] = ((a0.w + a1.w) + (a2.w + a3.w)) + bb.w;
        }
        if ((tid & 7) == 0)
            op[DD] = -((sDv[r] + sDv[ROWS + r]) + (sDv[2 * ROWS + r] + sDv[3 * ROWS + r]));
    }
}

extern "C" void kernel_launch(void* const* d_in, const int* in_sizes, int n_in,
                              void* d_out, int out_size) {
    const float* t  = (const float*)d_in[0];
    const float* y  = (const float*)d_in[1];
    const float* W1 = (const float*)d_in[2];
    const float* b1 = (const float*)d_in[3];
    const float* wt = (const float*)d_in[4];
    const float* W2 = (const float*)d_in[5];
    const float* b2 = (const float*)d_in[6];
    float* out = (float*)d_out;

    const int n = in_sizes[1] / DD;          // 8192
    const int blocks = n / ROWS;             // 128

    ode_prep<<<64, 256>>>(t, W1, b1, wt, W2, b2);
    cudaFuncSetAttribute(ode_mma,
                         cudaFuncAttributeMaxDynamicSharedMemorySize, SMEM_TOTAL);
    ode_mma<<<blocks, THREADS, SMEM_TOTAL>>>(y, out);
}

// round 13
// speedup vs baseline: 3.1799x; 1.0985x over previous
#include <cuda_runtime.h>
#include <cuda_bf16.h>
#include <cstdint>

#define DD 64
#define HH 256
#define ROWS 64            // rows per CTA
#define THREADS 512        // 16 warps = 4 row-stripes x 4 jj-parts

// padded bf16 strides (elements)
#define YSTR  136
#define W1STR 136
#define W2STR 520

#define W1IMG_BYTES (HH * W1STR * 2)   // 69632
#define W2IMG_BYTES (DD * W2STR * 2)   // 66560

#define SM_Y   0
#define SM_W1  (SM_Y  + ROWS * YSTR * 2)          // 17408
#define SM_W2  (SM_W1 + W1IMG_BYTES)              // 87040
#define SM_Z   (SM_W2 + W2IMG_BYTES)              // 153600
#define SM_S   (SM_Z + HH * 4)
#define SM_B2  (SM_S + HH * 4)
#define SMEM_TOTAL (SM_B2 + DD * 4 + 16)

// post-mainloop reuse of [SM_Y .. SM_W2): partials + div partials
// sP stride padded to 68 floats -> row-to-row bank shift of 4 (kills 8-way conflicts)
#define PSTR   68
#define SM_P   0                            // float [4][64][PSTR] = 69632 B
#define SM_DV  (4 * ROWS * PSTR * 4)        // float [4][64] = 1024 B (fits < 87040)

__device__ __align__(16) unsigned char g_w1img[W1IMG_BYTES];
__device__ __align__(16) unsigned char g_w2img[W2IMG_BYTES];
__device__ __align__(16) float g_z[HH];
__device__ __align__(16) float g_s[HH];
__device__ __align__(16) float g_b2[DD];

__device__ __forceinline__ uint32_t smem_u32(const void* p) {
    uint32_t a;
    asm("{ .reg .u64 t; cvta.to.shared.u64 t, %1; cvt.u32.u64 %0, t; }" : "=r"(a) : "l"(p));
    return a;
}
__device__ __forceinline__ float tanh_ap(float x) {
    float r; asm("tanh.approx.f32 %0, %1;" : "=f"(r) : "f"(x)); return r;
}
__device__ __forceinline__ uint32_t packbf(float lo, float hi) {
    uint32_t r;
    asm("cvt.rn.bf16x2.f32 %0, %1, %2;" : "=r"(r) : "f"(hi), "f"(lo));
    return r;   // low 16 = lo operand
}
__device__ __forceinline__ void mma_bf16(float c[4], const uint32_t a[4], const uint32_t b[2]) {
    asm volatile("mma.sync.aligned.m16n8k16.row.col.f32.bf16.bf16.f32 "
        "{%0,%1,%2,%3}, {%4,%5,%6,%7}, {%8,%9}, {%0,%1,%2,%3};"
        : "+f"(c[0]), "+f"(c[1]), "+f"(c[2]), "+f"(c[3])
        : "r"(a[0]), "r"(a[1]), "r"(a[2]), "r"(a[3]), "r"(b[0]), "r"(b[1]));
}
#define LDM4(R, addr) asm volatile( \
    "ldmatrix.sync.aligned.m8n8.x4.shared.b16 {%0,%1,%2,%3}, [%4];" \
    : "=r"((R)[0]), "=r"((R)[1]), "=r"((R)[2]), "=r"((R)[3]) : "r"(addr))

// ============ prep kernel: convert weights once (fully parallel) ============
__global__ __launch_bounds__(256, 1)
void ode_prep(const float* __restrict__ tptr, const float* __restrict__ W1,
              const float* __restrict__ b1, const float* __restrict__ wt,
              const float* __restrict__ W2, const float* __restrict__ b2)
{
    const int gidx = blockIdx.x * 256 + threadIdx.x;   // 0..16383 (grid 64)
    __nv_bfloat16* w1i = (__nv_bfloat16*)g_w1img;
    __nv_bfloat16* w2i = (__nv_bfloat16*)g_w2img;
    {   // W1 [d][j] -> image[j][d | 64+d]
        int d = gidx >> 8, j = gidx & 255;
        float v = W1[gidx];
        __nv_bfloat16 h = __float2bfloat16(v);
        w1i[j * W1STR + d]      = h;
        w1i[j * W1STR + 64 + d] = __float2bfloat16(v - __bfloat162float(h));
    }
    {   // W2 [hr][n] -> image[n][hr | 256+hr]
        int hr = gidx >> 6, n = gidx & 63;
        float v = W2[gidx];
        __nv_bfloat16 h = __float2bfloat16(v);
        w2i[n * W2STR + hr]       = h;
        w2i[n * W2STR + 256 + hr] = __float2bfloat16(v - __bfloat162float(h));
    }
    // s_j: warp-per-j reduction
    if (gidx < 8192) {
        const int j = gidx >> 5, d = gidx & 31;
        float p = W1[d * HH + j] * W2[j * DD + d]
                + W1[(d + 32) * HH + j] * W2[j * DD + d + 32];
        p += __shfl_xor_sync(0xffffffffu, p, 1);
        p += __shfl_xor_sync(0xffffffffu, p, 2);
        p += __shfl_xor_sync(0xffffffffu, p, 4);
        p += __shfl_xor_sync(0xffffffffu, p, 8);
        p += __shfl_xor_sync(0xffffffffu, p, 16);
        if (d == 0) g_s[j] = p;
    }
    if (gidx < HH) g_z[gidx] = tptr[0] * wt[gidx] + b1[gidx];
    if (gidx < DD) g_b2[gidx] = b2[gidx];
}

// ============ main kernel ============
__global__ __launch_bounds__(THREADS, 1)
void ode_mma(const float* __restrict__ y, float* __restrict__ out)
{
    extern __shared__ char smc[];
    float* sz  = (float*)(smc + SM_Z);
    float* ss  = (float*)(smc + SM_S);
    float* sbb = (float*)(smc + SM_B2);

    const uint32_t sbase = smem_u32(smc);
    const int tid  = threadIdx.x;
    const int lane = tid & 31;
    const int warp = tid >> 5;
    const int stripe = warp & 3;          // 16-row stripe
    const int part   = warp >> 2;         // jj quarter (0..3)

    // ---- prologue: flat image copies + vectorized Y convert ----
    {
        const float4* s1 = (const float4*)g_w1img;
        float4* d1 = (float4*)(smc + SM_W1);
        #pragma unroll
        for (int i = tid; i < W1IMG_BYTES / 16; i += THREADS) d1[i] = s1[i];
        const float4* s2 = (const float4*)g_w2img;
        float4* d2 = (float4*)(smc + SM_W2);
        #pragma unroll
        for (int i = tid; i < W2IMG_BYTES / 16; i += THREADS) d2[i] = s2[i];
        if (tid < HH) { sz[tid] = g_z[tid]; ss[tid] = g_s[tid]; }
        if (tid < DD) sbb[tid] = g_b2[tid];

        const float2* yb = (const float2*)(y + (size_t)blockIdx.x * ROWS * DD);
        uint32_t* sy32 = (uint32_t*)(smc + SM_Y);
        #pragma unroll
        for (int i = tid; i < ROWS * DD / 2; i += THREADS) {
            const int r = i >> 5, dp = (i & 31);
            float2 v = yb[i];
            uint32_t u0 = __float_as_uint(v.x), u1 = __float_as_uint(v.y);
            uint32_t hi = __byte_perm(u0, u1, 0x7632);
            float l0 = v.x - __uint_as_float(u0 & 0xFFFF0000u);
            float l1 = v.y - __uint_as_float(u1 & 0xFFFF0000u);
            sy32[r * (YSTR / 2) + dp]      = hi;
            sy32[r * (YSTR / 2) + 32 + dp] = packbf(l0, l1);
        }
    }
    __syncthreads();

    // ---- per-warp: 16-row stripe, quarter of hidden dim ----
    const int r0 = stripe * 16;

    uint32_t yhi[4][4], ylo[4][4];
    {
        const int arow = r0 + (lane & 7) + ((lane >> 3) & 1) * 8;
        const int acol = ((lane >> 4) & 1) * 8;
        const uint32_t abase = sbase + SM_Y + (uint32_t)arow * (YSTR * 2);
        #pragma unroll
        for (int kk = 0; kk < 4; kk++) {
            LDM4(yhi[kk], abase + (uint32_t)(kk * 16 + acol) * 2);
            LDM4(ylo[kk], abase + (uint32_t)(64 + kk * 16 + acol) * 2);
        }
    }

    float acc2[8][4];
    #pragma unroll
    for (int t = 0; t < 8; t++)
        #pragma unroll
        for (int i = 0; i < 4; i++) acc2[t][i] = 0.f;
    float dvlo = 0.f, dvhi = 0.f;

    const int qq = (lane & 3) * 2;
    const uint32_t w1lo_off = (uint32_t)(lane & 7) * (W1STR * 2)
        + (uint32_t)(((lane >> 3) & 1) * 8 + ((lane >> 4) & 1) * 64) * 2;
    const uint32_t w2lo_off = (uint32_t)(lane & 7) * (W2STR * 2)
        + (uint32_t)(((lane >> 3) & 1) * 8 + ((lane >> 4) & 1) * 256) * 2;

    const int jjBeg = part * 4;
    // FULLY UNROLLED jj loop: lets ptxas overlap next-jj LDSM/GEMM1 with
    // current epilogue/GEMM2 (the serialization seam at issue=17%)
    #pragma unroll
    for (int u = 0; u < 4; u++) {
        const int jj = jjBeg + u;

        // ---- GEMM1: 3 independent chains per n8 fragment ----
        float cfA[2][4], cfB[2][4], cfC[2][4];
        #pragma unroll
        for (int p = 0; p < 2; p++) {
            const int j0p = jj * 16 + p * 8;
            float2 zz = *(const float2*)(sz + j0p + qq);
            cfA[p][0] = zz.x; cfA[p][1] = zz.y; cfA[p][2] = zz.x; cfA[p][3] = zz.y;
            #pragma unroll
            for (int i = 0; i < 4; i++) { cfB[p][i] = 0.f; cfC[p][i] = 0.f; }

            const uint32_t bbase = sbase + SM_W1 + (uint32_t)j0p * (W1STR * 2) + w1lo_off;
            #pragma unroll
            for (int kk = 0; kk < 4; kk++) {
                uint32_t bf[4];                      // [0:2)=hi, [2:4)=lo
                LDM4(bf, bbase + (uint32_t)kk * 32);
                mma_bf16(cfA[p], yhi[kk], bf);
                mma_bf16(cfB[p], ylo[kk], bf);
                mma_bf16(cfC[p], yhi[kk], bf + 2);
            }
        }

        // ---- epilogue-1: tanh + cheap truncation split ----
        uint32_t Ah[4], Al[4];
        float hv[2][4];
        #pragma unroll
        for (int p = 0; p < 2; p++) {
            float h0 = tanh_ap((cfA[p][0] + cfB[p][0]) + cfC[p][0]);
            float h1 = tanh_ap((cfA[p][1] + cfB[p][1]) + cfC[p][1]);
            float h2 = tanh_ap((cfA[p][2] + cfB[p][2]) + cfC[p][2]);
            float h3 = tanh_ap((cfA[p][3] + cfB[p][3]) + cfC[p][3]);
            hv[p][0] = h0; hv[p][1] = h1; hv[p][2] = h2; hv[p][3] = h3;
            uint32_t u0 = __float_as_uint(h0), u1 = __float_as_uint(h1);
            uint32_t u2 = __float_as_uint(h2), u3 = __float_as_uint(h3);
            Ah[p * 2 + 0] = __byte_perm(u0, u1, 0x7632);
            Ah[p * 2 + 1] = __byte_perm(u2, u3, 0x7632);
            Al[p * 2 + 0] = packbf(h0 - __uint_as_float(u0 & 0xFFFF0000u),
                                   h1 - __uint_as_float(u1 & 0xFFFF0000u));
            Al[p * 2 + 1] = packbf(h2 - __uint_as_float(u2 & 0xFFFF0000u),
                                   h3 - __uint_as_float(u3 & 0xFFFF0000u));
        }

        // ---- GEMM2: 8 independent chains ----
        const uint32_t b2base = sbase + SM_W2 + (uint32_t)(jj * 16) * 2 + w2lo_off;
        #pragma unroll
        for (int t = 0; t < 8; t++) {
            uint32_t bf[4];
            LDM4(bf, b2base + (uint32_t)t * 8 * (W2STR * 2));
            mma_bf16(acc2[t], Ah, bf);
            mma_bf16(acc2[t], Al, bf);
            mma_bf16(acc2[t], Ah, bf + 2);
        }

        // ---- divergence FMAs (independent; fill MMA stalls) ----
        #pragma unroll
        for (int p = 0; p < 2; p++) {
            float2 sv = *(const float2*)(ss + jj * 16 + p * 8 + qq);
            dvlo += (1.f - hv[p][0] * hv[p][0]) * sv.x + (1.f - hv[p][1] * hv[p][1]) * sv.y;
            dvhi += (1.f - hv[p][2] * hv[p][2]) * sv.x + (1.f - hv[p][3] * hv[p][3]) * sv.y;
        }
    }

    // ---- combine the 4 jj-quarters via smem (PSTR-padded, conflict-light) ----
    __syncthreads();
    {
        float* sP  = (float*)(smc + SM_P);   // [4][64][PSTR]
        float* sDv = (float*)(smc + SM_DV);  // [4][64]
        const int rA = r0 + (lane >> 2);
        const int rB = rA + 8;
        float* pA = sP + ((size_t)part * ROWS + rA) * PSTR + qq;
        float* pB = sP + ((size_t)part * ROWS + rB) * PSTR + qq;
        #pragma unroll
        for (int t = 0; t < 8; t++) {
            *(float2*)(pA + t * 8) = make_float2(acc2[t][0], acc2[t][1]);
            *(float2*)(pB + t * 8) = make_float2(acc2[t][2], acc2[t][3]);
        }
        dvlo += __shfl_xor_sync(0xffffffffu, dvlo, 1);
        dvlo += __shfl_xor_sync(0xffffffffu, dvlo, 2);
        dvhi += __shfl_xor_sync(0xffffffffu, dvhi, 1);
        dvhi += __shfl_xor_sync(0xffffffffu, dvhi, 2);
        if ((lane & 3) == 0) {
            sDv[part * ROWS + rA] = dvlo;
            sDv[part * ROWS + rB] = dvhi;
        }
    }
    __syncthreads();

    // ---- final: sum 4 partials + b2 -> out ----
    {
        const float* sP  = (const float*)(smc + SM_P);
        const float* sDv = (const float*)(smc + SM_DV);
        const int r  = tid >> 3;             // 0..63
        const int c0 = (tid & 7) * 8;
        float* op = out + (size_t)(blockIdx.x * ROWS + r) * (DD + 1);
        #pragma unroll
        for (int i = 0; i < 2; i++) {
            const int c = c0 + i * 4;
            float4 a0 = *(const float4*)(sP + (size_t)(0 * ROWS + r) * PSTR + c);
            float4 a1 = *(const float4*)(sP + (size_t)(1 * ROWS + r) * PSTR + c);
            float4 a2 = *(const float4*)(sP + (size_t)(2 * ROWS + r) * PSTR + c);
            float4 a3 = *(const float4*)(sP + (size_t)(3 * ROWS + r) * PSTR + c);
            float4 bb = *(const float4*)(sbb + c);
            op[c + 0] = ((a0.x + a1.x) + (a2.x + a3.x)) + bb.x;
            op[c + 1] = ((a0.y + a1.y) + (a2.y + a3.y)) + bb.y;
            op[c + 2] = ((a0.z + a1.z) + (a2.z + a3.z)) + bb.z;
            op[c + 3] = ((a0.w + a1.w) + (a2.w + a3.w)) + bb.w;
        }
        if ((tid & 7) == 0)
            op[DD] = -((sDv[r] + sDv[ROWS + r]) + (sDv[2 * ROWS + r] + sDv[3 * ROWS + r]));
    }
}

extern "C" void kernel_launch(void* const* d_in, const int* in_sizes, int n_in,
                              void* d_out, int out_size) {
    const float* t  = (const float*)d_in[0];
    const float* y  = (const float*)d_in[1];
    const float* W1 = (const float*)d_in[2];
    const float* b1 = (const float*)d_in[3];
    const float* wt = (const float*)d_in[4];
    const float* W2 = (const float*)d_in[5];
    const float* b2 = (const float*)d_in[6];
    float* out = (float*)d_out;

    const int n = in_sizes[1] / DD;          // 8192
    const int blocks = n / ROWS;             // 128

    ode_prep<<<64, 256>>>(t, W1, b1, wt, W2, b2);
    cudaFuncSetAttribute(ode_mma,
                         cudaFuncAttributeMaxDynamicSharedMemorySize, SMEM_TOTAL);
    ode_mma<<<blocks, THREADS, SMEM_TOTAL>>>(y, out);
}